// round 1
// baseline (speedup 1.0000x reference)
#include <cuda_runtime.h>
#include <math.h>

#define B_  16
#define C_  128
#define T_  16384
#define H_  4
#define D_  32

// ---------------- scratch (static device globals; no runtime alloc) ----------
__device__ float g_eq[B_ * C_ * T_];   // exp(q)          128 MB
__device__ float g_ek[B_ * C_ * T_];   // exp(k)          128 MB
__device__ float g_v [B_ * C_ * T_];   // v raw           128 MB
__device__ float g_op[B_ * C_ * T_];   // pre-GN output   128 MB
__device__ float g_Sq[B_ * C_];        // sum exp(q) per (b, h*32+d)
__device__ float g_Sk[B_ * C_];
__device__ float g_ctx[B_ * H_ * D_ * D_];  // raw k-v contraction
__device__ float g_M[B_ * C_ * C_];         // fused (W_out x ctx) matrix
__device__ float g_stats[B_ * 2];           // GN sum / sumsq

// ---------------- K0: zero accumulators --------------------------------------
__global__ void k_zero()
{
    int i = blockIdx.x * 256 + threadIdx.x;
    if (i < B_ * C_)            { g_Sq[i] = 0.f; g_Sk[i] = 0.f; }
    if (i < B_ * H_ * D_ * D_)  g_ctx[i]  = 0.f;
    if (i < B_ * 2)             g_stats[i] = 0.f;
}

// ---------------- K1: QKV GEMM + softmax-exp epilogue ------------------------
// C[o,t] = sum_c W[o,c] * x[b,c,t].  Block tile 128(o) x 128(t), BK=8,
// 256 threads, 8x8 register tile.  blockIdx.y selects q/k/v o-slab.
__global__ __launch_bounds__(256, 2) void k_qkv(const float* __restrict__ x,
                                                const float* __restrict__ wqkv)
{
    const int b  = blockIdx.z;
    const int ot = blockIdx.y;            // 0=q, 1=k, 2=v
    const int n0 = blockIdx.x * 128;

    const float* A  = wqkv + ot * (128 * 128);   // [128 o][128 c] row-major
    const float* Bm = x + b * (C_ * T_);         // [128 c][16384 t]

    __shared__ float As[8][128];
    __shared__ float Bs[8][128];
    __shared__ float rsum[128];

    const int tid = threadIdx.x;
    const int tx  = tid & 15;
    const int ty  = tid >> 4;

    float acc[8][8];
#pragma unroll
    for (int i = 0; i < 8; i++)
#pragma unroll
        for (int j = 0; j < 8; j++) acc[i][j] = 0.f;

    const int aRow = tid >> 1;
    const int aCol = (tid & 1) * 4;
    const int bRow = tid >> 5;
    const int bCol = (tid & 31) * 4;

    for (int k0 = 0; k0 < 128; k0 += 8) {
        float4 av = *(const float4*)(A + aRow * 128 + k0 + aCol);
        As[aCol + 0][aRow] = av.x;
        As[aCol + 1][aRow] = av.y;
        As[aCol + 2][aRow] = av.z;
        As[aCol + 3][aRow] = av.w;
        *(float4*)&Bs[bRow][bCol] =
            *(const float4*)(Bm + (k0 + bRow) * T_ + n0 + bCol);
        __syncthreads();
#pragma unroll
        for (int k = 0; k < 8; k++) {
            float a[8], bb[8];
            *(float4*)(a)      = *(const float4*)&As[k][ty * 8];
            *(float4*)(a + 4)  = *(const float4*)&As[k][ty * 8 + 4];
            *(float4*)(bb)     = *(const float4*)&Bs[k][tx * 8];
            *(float4*)(bb + 4) = *(const float4*)&Bs[k][tx * 8 + 4];
#pragma unroll
            for (int i = 0; i < 8; i++)
#pragma unroll
                for (int j = 0; j < 8; j++)
                    acc[i][j] = fmaf(a[i], bb[j], acc[i][j]);
        }
        __syncthreads();
    }

    if (ot == 2) {               // v: store raw
        float* dst = g_v + b * (C_ * T_);
#pragma unroll
        for (int i = 0; i < 8; i++) {
            int row = ty * 8 + i;
            float4 v1 = make_float4(acc[i][0], acc[i][1], acc[i][2], acc[i][3]);
            float4 v2 = make_float4(acc[i][4], acc[i][5], acc[i][6], acc[i][7]);
            *(float4*)(dst + row * T_ + n0 + tx * 8)     = v1;
            *(float4*)(dst + row * T_ + n0 + tx * 8 + 4) = v2;
        }
    } else {                     // q/k: store exp, accumulate row-sums
        float* dst = (ot == 0 ? g_eq : g_ek) + b * (C_ * T_);
        float* S   = (ot == 0 ? g_Sq : g_Sk) + b * C_;
        if (tid < 128) rsum[tid] = 0.f;
        __syncthreads();
#pragma unroll
        for (int i = 0; i < 8; i++) {
            int row = ty * 8 + i;
            float e[8];
            float rs = 0.f;
#pragma unroll
            for (int j = 0; j < 8; j++) { e[j] = expf(acc[i][j]); rs += e[j]; }
            float4 v1 = make_float4(e[0], e[1], e[2], e[3]);
            float4 v2 = make_float4(e[4], e[5], e[6], e[7]);
            *(float4*)(dst + row * T_ + n0 + tx * 8)     = v1;
            *(float4*)(dst + row * T_ + n0 + tx * 8 + 4) = v2;
            atomicAdd(&rsum[row], rs);
        }
        __syncthreads();
        if (tid < 128) atomicAdd(&S[tid], rsum[tid]);
    }
}

// ---------------- K2: ctx[b,h,d,e] = sum_n exp(k[d,n]) * v[e,n] --------------
// grid (32 n-splits, 4 h, 16 b); atomically accumulate raw contraction.
__global__ __launch_bounds__(256) void k_ctx()
{
    const int b = blockIdx.z, h = blockIdx.y, sp = blockIdx.x;
    const float* K = g_ek + (b * C_ + h * D_) * T_;
    const float* V = g_v  + (b * C_ + h * D_) * T_;
    __shared__ float ks[32][68];
    __shared__ float vs[32][68];
    const int tid = threadIdx.x;
    const int d   = tid >> 3;
    const int e0  = (tid & 7) * 4;
    float acc[4] = {0.f, 0.f, 0.f, 0.f};
    const int l = tid * 2;
    for (int n0 = sp * 512; n0 < sp * 512 + 512; n0 += 64) {
#pragma unroll
        for (int q = 0; q < 2; q++) {
            int li = l + q;
            int r  = li >> 4;
            int c4 = (li & 15) * 4;
            *(float4*)&ks[r][c4] = *(const float4*)(K + r * T_ + n0 + c4);
            *(float4*)&vs[r][c4] = *(const float4*)(V + r * T_ + n0 + c4);
        }
        __syncthreads();
#pragma unroll
        for (int j = 0; j < 64; j++) {
            float kd = ks[d][j];
            acc[0] = fmaf(kd, vs[e0 + 0][j], acc[0]);
            acc[1] = fmaf(kd, vs[e0 + 1][j], acc[1]);
            acc[2] = fmaf(kd, vs[e0 + 2][j], acc[2]);
            acc[3] = fmaf(kd, vs[e0 + 3][j], acc[3]);
        }
        __syncthreads();
    }
    float* Cp = g_ctx + ((b * H_ + h) * D_ + d) * D_ + e0;
    atomicAdd(Cp + 0, acc[0]);
    atomicAdd(Cp + 1, acc[1]);
    atomicAdd(Cp + 2, acc[2]);
    atomicAdd(Cp + 3, acc[3]);
}

// ---------------- K3: M[b][o][h*32+d] = sum_e W_out[o][h*32+e]*ctxf[h][d][e] -
// ctxf = scale * ctx / (S_k[d] * S_q[d]).   grid = 16 blocks (one per b).
__global__ __launch_bounds__(256) void k_M(const float* __restrict__ w_out)
{
    const int b = blockIdx.x;
    __shared__ float cf[4][32][32];
    const int tid = threadIdx.x;
    const float scale = 0.17677669529663687f;  // 32^-0.5
    for (int i = tid; i < H_ * D_ * D_; i += 256) {
        int h = i >> 10, d = (i >> 5) & 31;
        float cs = g_ctx[b * (H_ * D_ * D_) + i];
        float sk = g_Sk[b * C_ + h * D_ + d];
        float sq = g_Sq[b * C_ + h * D_ + d];
        ((float*)cf)[i] = scale * cs / (sk * sq);
    }
    __syncthreads();
    for (int i = tid; i < C_ * C_; i += 256) {
        int o = i >> 7, hd = i & 127;
        int h = hd >> 5, d = hd & 31;
        const float* wr = w_out + o * C_ + h * D_;
        float s = 0.f;
#pragma unroll
        for (int e = 0; e < 32; e++) s = fmaf(wr[e], cf[h][d][e], s);
        g_M[b * (C_ * C_) + i] = s;
    }
}

// ---------------- K4: out_pre = M[b] @ exp(q) + b_out; GN moments ------------
__global__ __launch_bounds__(256, 2) void k_out(const float* __restrict__ b_out)
{
    const int b  = blockIdx.z;
    const int n0 = blockIdx.x * 128;
    const float* A  = g_M  + b * (C_ * C_);
    const float* Bm = g_eq + b * (C_ * T_);
    __shared__ float As[8][128];
    __shared__ float Bs[8][128];
    const int tid = threadIdx.x;
    const int tx  = tid & 15;
    const int ty  = tid >> 4;

    float acc[8][8];
#pragma unroll
    for (int i = 0; i < 8; i++)
#pragma unroll
        for (int j = 0; j < 8; j++) acc[i][j] = 0.f;

    const int aRow = tid >> 1;
    const int aCol = (tid & 1) * 4;
    const int bRow = tid >> 5;
    const int bCol = (tid & 31) * 4;

    for (int k0 = 0; k0 < 128; k0 += 8) {
        float4 av = *(const float4*)(A + aRow * 128 + k0 + aCol);
        As[aCol + 0][aRow] = av.x;
        As[aCol + 1][aRow] = av.y;
        As[aCol + 2][aRow] = av.z;
        As[aCol + 3][aRow] = av.w;
        *(float4*)&Bs[bRow][bCol] =
            *(const float4*)(Bm + (k0 + bRow) * T_ + n0 + bCol);
        __syncthreads();
#pragma unroll
        for (int k = 0; k < 8; k++) {
            float a[8], bb[8];
            *(float4*)(a)      = *(const float4*)&As[k][ty * 8];
            *(float4*)(a + 4)  = *(const float4*)&As[k][ty * 8 + 4];
            *(float4*)(bb)     = *(const float4*)&Bs[k][tx * 8];
            *(float4*)(bb + 4) = *(const float4*)&Bs[k][tx * 8 + 4];
#pragma unroll
            for (int i = 0; i < 8; i++)
#pragma unroll
                for (int j = 0; j < 8; j++)
                    acc[i][j] = fmaf(a[i], bb[j], acc[i][j]);
        }
        __syncthreads();
    }

    float s1 = 0.f, s2 = 0.f;
    float* dst = g_op + b * (C_ * T_);
#pragma unroll
    for (int i = 0; i < 8; i++) {
        int row  = ty * 8 + i;
        float bo = b_out[row];
        float v[8];
#pragma unroll
        for (int j = 0; j < 8; j++) {
            v[j] = acc[i][j] + bo;
            s1 += v[j];
            s2 = fmaf(v[j], v[j], s2);
        }
        float4 v1 = make_float4(v[0], v[1], v[2], v[3]);
        float4 v2 = make_float4(v[4], v[5], v[6], v[7]);
        *(float4*)(dst + row * T_ + n0 + tx * 8)     = v1;
        *(float4*)(dst + row * T_ + n0 + tx * 8 + 4) = v2;
    }
#pragma unroll
    for (int off = 16; off > 0; off >>= 1) {
        s1 += __shfl_down_sync(0xffffffffu, s1, off);
        s2 += __shfl_down_sync(0xffffffffu, s2, off);
    }
    if ((tid & 31) == 0) {
        atomicAdd(&g_stats[b * 2 + 0], s1);
        atomicAdd(&g_stats[b * 2 + 1], s2);
    }
}

// ---------------- K5: GroupNorm finalize -------------------------------------
__global__ void k_norm(const float* __restrict__ gnw,
                       const float* __restrict__ gnb,
                       float* __restrict__ out)
{
    int i4 = blockIdx.x * 256 + threadIdx.x;
    int e  = i4 * 4;
    int b  = e >> 21;            // C_*T_ = 2^21
    int c  = (e >> 14) & 127;    // T_ = 2^14
    const float inv = 1.0f / (float)(C_ * T_);
    float m    = g_stats[b * 2 + 0] * inv;
    float var  = g_stats[b * 2 + 1] * inv - m * m;
    float rstd = rsqrtf(var + 1e-5f);
    float w    = gnw[c] * rstd;
    float bias = gnb[c] - m * w;
    float4 v = *(const float4*)(g_op + e);
    v.x = v.x * w + bias;
    v.y = v.y * w + bias;
    v.z = v.z * w + bias;
    v.w = v.w * w + bias;
    *(float4*)(out + e) = v;
}

// ---------------- launch ------------------------------------------------------
extern "C" void kernel_launch(void* const* d_in, const int* in_sizes, int n_in,
                              void* d_out, int out_size)
{
    const float* x    = (const float*)d_in[0];
    const float* wqkv = (const float*)d_in[1];
    const float* wout = (const float*)d_in[2];
    const float* bout = (const float*)d_in[3];
    const float* gnw  = (const float*)d_in[4];
    const float* gnb  = (const float*)d_in[5];
    float* out = (float*)d_out;

    k_zero<<<256, 256>>>();
    k_qkv<<<dim3(128, 3, 16), 256>>>(x, wqkv);
    k_ctx<<<dim3(32, 4, 16), 256>>>();
    k_M<<<16, 256>>>(wout);
    k_out<<<dim3(128, 1, 16), 256>>>(bout);
    k_norm<<<32768, 256>>>(gnw, gnb, out);
}